// round 10
// baseline (speedup 1.0000x reference)
#include <cuda_runtime.h>
#include <cuda_fp16.h>
#include <cstdint>

#define NN     100000
#define HH     128
#define TT     32
#define MDIM   16
#define ES     600000
#define ED     600000

// ---------------- scratch ----------------
__device__ __align__(16) __half g_Ps[NN * TT];   // fp16 x@W[:H]
__device__ __align__(16) __half g_Pd[NN * TT];   // fp16 x@W[H:] + b_trans
// packed edge records: (src, dst, ew_bits, 0)
__device__ __align__(16) uint4 g_pk_s[ES];
__device__ __align__(16) uint4 g_pk_d[ED];
// propagation state: fp32 accumulator (atomics) + fp16 read mirror
__device__ __align__(32) float  g_n32pos[NN * MDIM];
__device__ __align__(32) float  g_n32dom[NN * MDIM];
__device__ __align__(32) __half g_c16pos[NN * MDIM];
__device__ __align__(32) __half g_c16dom[NN * MDIM];
// "dst row saw an atomic attempt in round 2" flags (conservative, exact skip)
__device__ unsigned char g_fpos[NN];
__device__ unsigned char g_fdom[NN];

// ---------------- helpers ----------------
__device__ __forceinline__ float fast_tanh(float s) {
    float r; asm("tanh.approx.f32 %0, %1;" : "=f"(r) : "f"(s)); return r;
}
__device__ __forceinline__ unsigned su32(const void* p) {
    return (unsigned)__cvta_generic_to_shared(p);
}

// ---------------- kernel 1: HMMA node projections --------------------------
#define XS_STRIDE 136
#define WP_STRIDE 72

__global__ void __launch_bounds__(128) proj_kernel(const float* __restrict__ x,
                                                   const float* __restrict__ Wt,
                                                   const float* __restrict__ bt) {
    __shared__ __align__(16) __half Wp[128 * WP_STRIDE];
    __shared__ __align__(16) __half xs[64 * XS_STRIDE];
    int tid = threadIdx.x;
    int n0 = blockIdx.x * 64;

    for (int i = tid; i < 128 * 64; i += 128) {
        int h = i >> 6, j = i & 63;
        float w = (j < 32) ? Wt[h * 32 + j] : Wt[(128 + h) * 32 + (j - 32)];
        Wp[h * WP_STRIDE + j] = __float2half_rn(w);
    }
    for (int i = tid; i < 64 * 32; i += 128) {
        int r = i >> 5, c4 = i & 31;
        int node = n0 + r;
        float4 v = (node < NN)
                 ? reinterpret_cast<const float4*>(x)[(size_t)node * 32 + c4]
                 : make_float4(0.f, 0.f, 0.f, 0.f);
        *reinterpret_cast<__half2*>(&xs[r * XS_STRIDE + c4 * 4])     = __floats2half2_rn(v.x, v.y);
        *reinterpret_cast<__half2*>(&xs[r * XS_STRIDE + c4 * 4 + 2]) = __floats2half2_rn(v.z, v.w);
    }
    __syncthreads();

    int warp = tid >> 5, lane = tid & 31;
    int wb = warp * 16;

    float acc[8][4];
#pragma unroll
    for (int nt = 0; nt < 8; nt++)
#pragma unroll
        for (int j = 0; j < 4; j++) acc[nt][j] = 0.f;

    int a_row = wb + (lane & 15);
    int a_coff = (lane >> 4) * 8;
    int b_row = (lane & 15);

#pragma unroll
    for (int k = 0; k < 8; k++) {
        unsigned a0, a1, a2, a3;
        unsigned addrA = su32(&xs[a_row * XS_STRIDE + k * 16 + a_coff]);
        asm volatile("ldmatrix.sync.aligned.m8n8.x4.shared.b16 {%0,%1,%2,%3}, [%4];"
                     : "=r"(a0), "=r"(a1), "=r"(a2), "=r"(a3) : "r"(addrA));
#pragma unroll
        for (int nt = 0; nt < 8; nt++) {
            unsigned b0, b1;
            unsigned addrB = su32(&Wp[(k * 16 + b_row) * WP_STRIDE + nt * 8]);
            asm volatile("ldmatrix.sync.aligned.m8n8.x2.trans.shared.b16 {%0,%1}, [%2];"
                         : "=r"(b0), "=r"(b1) : "r"(addrB));
            asm volatile("mma.sync.aligned.m16n8k16.row.col.f32.f16.f16.f32 "
                         "{%0,%1,%2,%3}, {%4,%5,%6,%7}, {%8,%9}, {%0,%1,%2,%3};"
                         : "+f"(acc[nt][0]), "+f"(acc[nt][1]), "+f"(acc[nt][2]), "+f"(acc[nt][3])
                         : "r"(a0), "r"(a1), "r"(a2), "r"(a3), "r"(b0), "r"(b1));
        }
    }

    int row_l = wb + (lane >> 2);
    int col0 = (lane & 3) * 2;
#pragma unroll
    for (int nt = 0; nt < 8; nt++) {
        bool isPs = (nt < 4);
        __half* base = isPs ? g_Ps : g_Pd;
        int cc = isPs ? (nt * 8 + col0) : (nt * 8 + col0 - 32);
        float b0 = isPs ? 0.f : bt[cc];
        float b1 = isPs ? 0.f : bt[cc + 1];
        int nodeA = n0 + row_l;
        int nodeB = nodeA + 8;
        if (nodeA < NN)
            *reinterpret_cast<__half2*>(&base[(size_t)nodeA * TT + cc]) =
                __floats2half2_rn(acc[nt][0] + b0, acc[nt][1] + b1);
        if (nodeB < NN)
            *reinterpret_cast<__half2*>(&base[(size_t)nodeB * TT + cc]) =
                __floats2half2_rn(acc[nt][2] + b0, acc[nt][3] + b1);
    }
}

// ---------------- kernel 2: init: mask -> n32 (fp32) + c16 (fp16) ---------
__global__ void init_kernel(const float* __restrict__ mask) {
    int i = blockIdx.x * blockDim.x + threadIdx.x;
    const int n4 = NN * MDIM / 4;
    if (i >= n4) return;
    float4 v = reinterpret_cast<const float4*>(mask)[i];
    reinterpret_cast<float4*>(g_n32pos)[i] = v;
    reinterpret_cast<float4*>(g_n32dom)[i] = v;
    __half2 h0 = __floats2half2_rn(v.x, v.y);
    __half2 h1 = __floats2half2_rn(v.z, v.w);
    uint2 packed = make_uint2(*reinterpret_cast<unsigned*>(&h0), *reinterpret_cast<unsigned*>(&h1));
    reinterpret_cast<uint2*>(g_c16pos)[i] = packed;
    reinterpret_cast<uint2*>(g_c16dom)[i] = packed;
}

// ---------------- kernel 3: FUSED gate + round-1 prop + edge packing -------
__global__ void ewprop_kernel(const int* __restrict__ si, const int* __restrict__ di,
                              const float* __restrict__ sattr, const float* __restrict__ dattr,
                              const float* __restrict__ Wpos, const float* __restrict__ bpos,
                              const float* __restrict__ Wdom, const float* __restrict__ bdom) {
    long long gid = (long long)blockIdx.x * blockDim.x + threadIdx.x;
    long long eg = gid >> 2;
    int sub = (int)(gid & 3);
    if (eg >= (long long)(ES + ED)) return;

    bool spatial = (eg < ES);
    int e = spatial ? (int)eg : (int)(eg - ES);
    const int* eidx = spatial ? si : di;
    int nE = spatial ? ES : ED;
    int src = eidx[e];
    int dst = eidx[nE + e];

    uint4 psr = *reinterpret_cast<const uint4*>(&g_Ps[(size_t)src * TT + sub * 8]);
    uint4 pdr = *reinterpret_cast<const uint4*>(&g_Pd[(size_t)dst * TT + sub * 8]);
    const __half2* ph = reinterpret_cast<const __half2*>(&psr);
    const __half2* qh = reinterpret_cast<const __half2*>(&pdr);

    float th[8];
#pragma unroll
    for (int j = 0; j < 4; j++) {
        float2 a = __half22float2(ph[j]);
        float2 b = __half22float2(qh[j]);
        th[2 * j]     = fast_tanh(a.x + b.x);
        th[2 * j + 1] = fast_tanh(a.y + b.y);
    }

    float part = 0.f;
    if (spatial) {
        const float* w = &Wpos[4 + sub * 8];
#pragma unroll
        for (int j = 0; j < 8; j++) part += th[j] * w[j];
        if (sub == 0) {
            float4 a = *reinterpret_cast<const float4*>(&sattr[(size_t)e * 4]);
            part += a.x * Wpos[0] + a.y * Wpos[1] + a.z * Wpos[2] + a.w * Wpos[3];
        }
    } else {
        const float* w = &Wdom[1 + sub * 8];
#pragma unroll
        for (int j = 0; j < 8; j++) part += th[j] * w[j];
        if (sub == 0) part += dattr[e] * Wdom[0];
    }

    part += __shfl_xor_sync(0xFFFFFFFFu, part, 1);
    part += __shfl_xor_sync(0xFFFFFFFFu, part, 2);

    float logit = part + (spatial ? bpos[0] : bdom[0]);
    float ew = 1.f / (1.f + __expf(-logit));
    if (sub == 0) {
        uint4 rec = make_uint4((unsigned)src, (unsigned)dst, __float_as_uint(ew), 0u);
        if (spatial) g_pk_s[e] = rec; else g_pk_d[e] = rec;
    }

    // ---- fused round-1 propagation: 4 lanes x 4 channels ----
    {
        const __half* c = spatial ? g_c16pos : g_c16dom;
        float* n = spatial ? g_n32pos : g_n32dom;
        uint2 sr = *reinterpret_cast<const uint2*>(&c[(size_t)src * MDIM + sub * 4]);
        uint2 dr = *reinterpret_cast<const uint2*>(&c[(size_t)dst * MDIM + sub * 4]);
        const __half2* sh = reinterpret_cast<const __half2*>(&sr);
        const __half2* dh = reinterpret_cast<const __half2*>(&dr);
        unsigned int* dn = reinterpret_cast<unsigned int*>(&n[(size_t)dst * MDIM + sub * 4]);
#pragma unroll
        for (int j = 0; j < 2; j++) {
            float2 s = __half22float2(sh[j]);
            float2 d = __half22float2(dh[j]);
            float v0 = s.x * ew, v1 = s.y * ew;
            if (v0 > d.x) atomicMax(dn + 2 * j + 0, __float_as_uint(v0));
            if (v1 > d.y) atomicMax(dn + 2 * j + 1, __float_as_uint(v1));
        }
    }
}

// ---------------- kernel 4: convert n32 -> c16 (+ optional flag zero) ------
template <bool ZERO_FLAGS>
__global__ void convert_kernel() {
    int i = blockIdx.x * blockDim.x + threadIdx.x;
    const int n4 = NN * MDIM / 4;
    if (i >= n4) return;
    float4 p = reinterpret_cast<const float4*>(g_n32pos)[i];
    float4 d = reinterpret_cast<const float4*>(g_n32dom)[i];
    __half2 p0 = __floats2half2_rn(p.x, p.y);
    __half2 p1 = __floats2half2_rn(p.z, p.w);
    __half2 d0 = __floats2half2_rn(d.x, d.y);
    __half2 d1 = __floats2half2_rn(d.z, d.w);
    reinterpret_cast<uint2*>(g_c16pos)[i] =
        make_uint2(*reinterpret_cast<unsigned*>(&p0), *reinterpret_cast<unsigned*>(&p1));
    reinterpret_cast<uint2*>(g_c16dom)[i] =
        make_uint2(*reinterpret_cast<unsigned*>(&d0), *reinterpret_cast<unsigned*>(&d1));
    if (ZERO_FLAGS && i < NN) { g_fpos[i] = 0; g_fdom[i] = 0; }
}

// ---------------- kernel 5: prop rounds 2-3 (packed records) ---------------
// 2 lanes/edge-pair (one spatial + one dom edge per lane pair).
// Round 2 (WRITE_FLAGS): mark dst rows that saw any atomic attempt.
// Round 3 (READ_FLAGS): skip edges whose src saw no round-2 attempts (exact).
template <bool WRITE_FLAGS, bool READ_FLAGS>
__global__ void prop_kernel() {
    long long t = (long long)blockIdx.x * blockDim.x + threadIdx.x;
    if (t >= (long long)ES * 2) return;
    int p = (int)(t >> 1);
    int sub = (int)(t & 1);

    uint4 r0 = g_pk_s[p];
    uint4 r1 = g_pk_d[p];
    int s0 = (int)r0.x, d0 = (int)r0.y; float ew0 = __uint_as_float(r0.z);
    int s1 = (int)r1.x, d1 = (int)r1.y; float ew1 = __uint_as_float(r1.z);

    bool a0 = true, a1 = true;
    if (READ_FLAGS) {
        a0 = g_fpos[s0] != 0;
        a1 = g_fdom[s1] != 0;
        if (!(a0 | a1)) return;
    }

    if (a0) {
        uint4 sr = *reinterpret_cast<const uint4*>(&g_c16pos[(size_t)s0 * MDIM + sub * 8]);
        uint4 dr = *reinterpret_cast<const uint4*>(&g_c16pos[(size_t)d0 * MDIM + sub * 8]);
        const __half2* sh = reinterpret_cast<const __half2*>(&sr);
        const __half2* dh = reinterpret_cast<const __half2*>(&dr);
        unsigned int* dn = reinterpret_cast<unsigned int*>(&g_n32pos[(size_t)d0 * MDIM + sub * 8]);
        bool att = false;
#pragma unroll
        for (int j = 0; j < 4; j++) {
            float2 s = __half22float2(sh[j]);
            float2 d = __half22float2(dh[j]);
            float v0 = s.x * ew0, v1 = s.y * ew0;
            if (v0 > d.x) { atomicMax(dn + 2 * j + 0, __float_as_uint(v0)); att = true; }
            if (v1 > d.y) { atomicMax(dn + 2 * j + 1, __float_as_uint(v1)); att = true; }
        }
        if (WRITE_FLAGS && att) g_fpos[d0] = 1;
    }
    if (a1) {
        uint4 sr = *reinterpret_cast<const uint4*>(&g_c16dom[(size_t)s1 * MDIM + sub * 8]);
        uint4 dr = *reinterpret_cast<const uint4*>(&g_c16dom[(size_t)d1 * MDIM + sub * 8]);
        const __half2* sh = reinterpret_cast<const __half2*>(&sr);
        const __half2* dh = reinterpret_cast<const __half2*>(&dr);
        unsigned int* dn = reinterpret_cast<unsigned int*>(&g_n32dom[(size_t)d1 * MDIM + sub * 8]);
        bool att = false;
#pragma unroll
        for (int j = 0; j < 4; j++) {
            float2 s = __half22float2(sh[j]);
            float2 d = __half22float2(dh[j]);
            float v0 = s.x * ew1, v1 = s.y * ew1;
            if (v0 > d.x) { atomicMax(dn + 2 * j + 0, __float_as_uint(v0)); att = true; }
            if (v1 > d.y) { atomicMax(dn + 2 * j + 1, __float_as_uint(v1)); att = true; }
        }
        if (WRITE_FLAGS && att) g_fdom[d1] = 1;
    }
}

// ---------------- kernel 6: final max --------------------------------------
__global__ void final_kernel(const float* __restrict__ mask, float* __restrict__ out) {
    int i = blockIdx.x * blockDim.x + threadIdx.x;
    const int n4 = NN * MDIM / 4;
    if (i >= n4) return;
    float4 m = reinterpret_cast<const float4*>(mask)[i];
    float4 p = reinterpret_cast<const float4*>(g_n32pos)[i];
    float4 d = reinterpret_cast<const float4*>(g_n32dom)[i];
    float4 r;
    r.x = fmaxf(m.x, fmaxf(p.x, d.x));
    r.y = fmaxf(m.y, fmaxf(p.y, d.y));
    r.z = fmaxf(m.z, fmaxf(p.z, d.z));
    r.w = fmaxf(m.w, fmaxf(p.w, d.w));
    reinterpret_cast<float4*>(out)[i] = r;
}

// ---------------- launch -------------------------------------------------
extern "C" void kernel_launch(void* const* d_in, const int* in_sizes, int n_in,
                              void* d_out, int out_size) {
    const float* x     = (const float*)d_in[0];
    const float* mask  = (const float*)d_in[1];
    const int*   si    = (const int*)d_in[2];
    const int*   di    = (const int*)d_in[3];
    const float* sattr = (const float*)d_in[4];
    const float* dattr = (const float*)d_in[5];
    const float* Wt    = (const float*)d_in[6];
    const float* bt    = (const float*)d_in[7];
    const float* Wpos  = (const float*)d_in[8];
    const float* bpos  = (const float*)d_in[9];
    const float* Wdom  = (const float*)d_in[10];
    const float* bdom  = (const float*)d_in[11];
    float* out = (float*)d_out;

    const int n4 = NN * MDIM / 4;
    const int cgrid = (n4 + 255) / 256;

    // 1. HMMA node projections (bias folded into Pd)
    proj_kernel<<<(NN + 63) / 64, 128>>>(x, Wt, bt);

    // 2. init: mask -> fp32 accumulators + fp16 mirrors
    init_kernel<<<cgrid, 256>>>(mask);

    // 3. fused gate + round-1 prop + edge-record packing
    {
        long long threads = (long long)(ES + ED) * 4;
        int blk = 256;
        long long grid = (threads + blk - 1) / blk;
        ewprop_kernel<<<(unsigned)grid, blk>>>(si, di, sattr, dattr, Wpos, bpos, Wdom, bdom);
    }

    // 4. rounds 2-3
    {
        long long threads = (long long)ES * 2;
        int blk = 256;
        long long grid = (threads + blk - 1) / blk;

        convert_kernel<true><<<cgrid, 256>>>();               // refresh mirrors + zero flags
        prop_kernel<true, false><<<(unsigned)grid, blk>>>();  // round 2: mark attempted dsts
        convert_kernel<false><<<cgrid, 256>>>();              // refresh mirrors
        prop_kernel<false, true><<<(unsigned)grid, blk>>>();  // round 3: skip unchanged srcs
    }

    // 5. final: max(mask, pos, dom)
    final_kernel<<<cgrid, 256>>>(mask, out);
}

// round 11
// speedup vs baseline: 1.5362x; 1.5362x over previous
#include <cuda_runtime.h>
#include <cuda_fp16.h>
#include <cstdint>

#define NN     100000
#define HH     128
#define TT     32
#define MDIM   16
#define ES     600000
#define ED     600000

// ---------------- scratch ----------------
__device__ __align__(16) __half g_Ps[NN * TT];   // fp16 x@W[:H]
__device__ __align__(16) __half g_Pd[NN * TT];   // fp16 x@W[H:] + b_trans
__device__ float g_ew_s[ES];
__device__ float g_ew_d[ED];
// propagation state: fp32 accumulator (atomics) + fp16 read mirror
__device__ __align__(16) float  g_n32pos[NN * MDIM];
__device__ __align__(16) float  g_n32dom[NN * MDIM];
__device__ __align__(16) __half g_c16pos[NN * MDIM];
__device__ __align__(16) __half g_c16dom[NN * MDIM];

// ---------------- helpers ----------------
__device__ __forceinline__ float fast_tanh(float s) {
    float r; asm("tanh.approx.f32 %0, %1;" : "=f"(r) : "f"(s)); return r;
}
__device__ __forceinline__ unsigned su32(const void* p) {
    return (unsigned)__cvta_generic_to_shared(p);
}

// ---------------- kernel 1: HMMA node projections + fused init -------------
// GEMM [NN,128] @ [128,64] fp16; also fans mask out to n32/c16 buffers
// (independent work overlapped with shared-memory staging).
#define XS_STRIDE 136
#define WP_STRIDE 72

__global__ void __launch_bounds__(128) proj_kernel(const float* __restrict__ x,
                                                   const float* __restrict__ Wt,
                                                   const float* __restrict__ bt,
                                                   const float* __restrict__ mask) {
    __shared__ __align__(16) __half Wp[128 * WP_STRIDE];
    __shared__ __align__(16) __half xs[64 * XS_STRIDE];
    int tid = threadIdx.x;
    int n0 = blockIdx.x * 64;

    // ---- fused init: mask -> n32 (fp32) + c16 (fp16), grid-stride ----
    {
        const int n4 = NN * MDIM / 4;
        for (int i = blockIdx.x * 128 + tid; i < n4; i += gridDim.x * 128) {
            float4 v = reinterpret_cast<const float4*>(mask)[i];
            reinterpret_cast<float4*>(g_n32pos)[i] = v;
            reinterpret_cast<float4*>(g_n32dom)[i] = v;
            __half2 h0 = __floats2half2_rn(v.x, v.y);
            __half2 h1 = __floats2half2_rn(v.z, v.w);
            uint2 packed = make_uint2(*reinterpret_cast<unsigned*>(&h0),
                                      *reinterpret_cast<unsigned*>(&h1));
            reinterpret_cast<uint2*>(g_c16pos)[i] = packed;
            reinterpret_cast<uint2*>(g_c16dom)[i] = packed;
        }
    }

    for (int i = tid; i < 128 * 64; i += 128) {
        int h = i >> 6, j = i & 63;
        float w = (j < 32) ? Wt[h * 32 + j] : Wt[(128 + h) * 32 + (j - 32)];
        Wp[h * WP_STRIDE + j] = __float2half_rn(w);
    }
    for (int i = tid; i < 64 * 32; i += 128) {
        int r = i >> 5, c4 = i & 31;
        int node = n0 + r;
        float4 v = (node < NN)
                 ? reinterpret_cast<const float4*>(x)[(size_t)node * 32 + c4]
                 : make_float4(0.f, 0.f, 0.f, 0.f);
        *reinterpret_cast<__half2*>(&xs[r * XS_STRIDE + c4 * 4])     = __floats2half2_rn(v.x, v.y);
        *reinterpret_cast<__half2*>(&xs[r * XS_STRIDE + c4 * 4 + 2]) = __floats2half2_rn(v.z, v.w);
    }
    __syncthreads();

    int warp = tid >> 5, lane = tid & 31;
    int wb = warp * 16;

    float acc[8][4];
#pragma unroll
    for (int nt = 0; nt < 8; nt++)
#pragma unroll
        for (int j = 0; j < 4; j++) acc[nt][j] = 0.f;

    int a_row = wb + (lane & 15);
    int a_coff = (lane >> 4) * 8;
    int b_row = (lane & 15);

#pragma unroll
    for (int k = 0; k < 8; k++) {
        unsigned a0, a1, a2, a3;
        unsigned addrA = su32(&xs[a_row * XS_STRIDE + k * 16 + a_coff]);
        asm volatile("ldmatrix.sync.aligned.m8n8.x4.shared.b16 {%0,%1,%2,%3}, [%4];"
                     : "=r"(a0), "=r"(a1), "=r"(a2), "=r"(a3) : "r"(addrA));
#pragma unroll
        for (int nt = 0; nt < 8; nt++) {
            unsigned b0, b1;
            unsigned addrB = su32(&Wp[(k * 16 + b_row) * WP_STRIDE + nt * 8]);
            asm volatile("ldmatrix.sync.aligned.m8n8.x2.trans.shared.b16 {%0,%1}, [%2];"
                         : "=r"(b0), "=r"(b1) : "r"(addrB));
            asm volatile("mma.sync.aligned.m16n8k16.row.col.f32.f16.f16.f32 "
                         "{%0,%1,%2,%3}, {%4,%5,%6,%7}, {%8,%9}, {%0,%1,%2,%3};"
                         : "+f"(acc[nt][0]), "+f"(acc[nt][1]), "+f"(acc[nt][2]), "+f"(acc[nt][3])
                         : "r"(a0), "r"(a1), "r"(a2), "r"(a3), "r"(b0), "r"(b1));
        }
    }

    int row_l = wb + (lane >> 2);
    int col0 = (lane & 3) * 2;
#pragma unroll
    for (int nt = 0; nt < 8; nt++) {
        bool isPs = (nt < 4);
        __half* base = isPs ? g_Ps : g_Pd;
        int cc = isPs ? (nt * 8 + col0) : (nt * 8 + col0 - 32);
        float b0 = isPs ? 0.f : bt[cc];
        float b1 = isPs ? 0.f : bt[cc + 1];
        int nodeA = n0 + row_l;
        int nodeB = nodeA + 8;
        if (nodeA < NN)
            *reinterpret_cast<__half2*>(&base[(size_t)nodeA * TT + cc]) =
                __floats2half2_rn(acc[nt][0] + b0, acc[nt][1] + b1);
        if (nodeB < NN)
            *reinterpret_cast<__half2*>(&base[(size_t)nodeB * TT + cc]) =
                __floats2half2_rn(acc[nt][2] + b0, acc[nt][3] + b1);
    }
}

// ---------------- kernel 2: FUSED gate + propagation round 1 ---------------
// 4 lanes/edge: gate over 32 channels (bias pre-folded into Pd), quad-reduce,
// then ALL 4 lanes do the round-1 filtered propagation (4 channels each).
__global__ void ewprop_kernel(const int* __restrict__ si, const int* __restrict__ di,
                              const float* __restrict__ sattr, const float* __restrict__ dattr,
                              const float* __restrict__ Wpos, const float* __restrict__ bpos,
                              const float* __restrict__ Wdom, const float* __restrict__ bdom) {
    long long gid = (long long)blockIdx.x * blockDim.x + threadIdx.x;
    long long eg = gid >> 2;
    int sub = (int)(gid & 3);
    if (eg >= (long long)(ES + ED)) return;

    bool spatial = (eg < ES);
    int e = spatial ? (int)eg : (int)(eg - ES);
    const int* eidx = spatial ? si : di;
    int nE = spatial ? ES : ED;
    int src = eidx[e];
    int dst = eidx[nE + e];

    uint4 psr = *reinterpret_cast<const uint4*>(&g_Ps[(size_t)src * TT + sub * 8]);
    uint4 pdr = *reinterpret_cast<const uint4*>(&g_Pd[(size_t)dst * TT + sub * 8]);
    const __half2* ph = reinterpret_cast<const __half2*>(&psr);
    const __half2* qh = reinterpret_cast<const __half2*>(&pdr);

    float th[8];
#pragma unroll
    for (int j = 0; j < 4; j++) {
        float2 a = __half22float2(ph[j]);
        float2 b = __half22float2(qh[j]);
        th[2 * j]     = fast_tanh(a.x + b.x);
        th[2 * j + 1] = fast_tanh(a.y + b.y);
    }

    float part = 0.f;
    if (spatial) {
        const float* w = &Wpos[4 + sub * 8];
#pragma unroll
        for (int j = 0; j < 8; j++) part += th[j] * w[j];
        if (sub == 0) {
            float4 a = *reinterpret_cast<const float4*>(&sattr[(size_t)e * 4]);
            part += a.x * Wpos[0] + a.y * Wpos[1] + a.z * Wpos[2] + a.w * Wpos[3];
        }
    } else {
        const float* w = &Wdom[1 + sub * 8];
#pragma unroll
        for (int j = 0; j < 8; j++) part += th[j] * w[j];
        if (sub == 0) part += dattr[e] * Wdom[0];
    }

    part += __shfl_xor_sync(0xFFFFFFFFu, part, 1);
    part += __shfl_xor_sync(0xFFFFFFFFu, part, 2);

    float logit = part + (spatial ? bpos[0] : bdom[0]);
    float ew = 1.f / (1.f + __expf(-logit));
    if (sub == 0) { if (spatial) g_ew_s[e] = ew; else g_ew_d[e] = ew; }

    // ---- fused round-1 propagation: 4 lanes x 4 channels ----
    {
        const __half* c = spatial ? g_c16pos : g_c16dom;
        float* n = spatial ? g_n32pos : g_n32dom;
        uint2 sr = *reinterpret_cast<const uint2*>(&c[(size_t)src * MDIM + sub * 4]);
        uint2 dr = *reinterpret_cast<const uint2*>(&c[(size_t)dst * MDIM + sub * 4]);
        const __half2* sh = reinterpret_cast<const __half2*>(&sr);
        const __half2* dh = reinterpret_cast<const __half2*>(&dr);
        unsigned int* dn = reinterpret_cast<unsigned int*>(&n[(size_t)dst * MDIM + sub * 4]);
#pragma unroll
        for (int j = 0; j < 2; j++) {
            float2 s = __half22float2(sh[j]);
            float2 d = __half22float2(dh[j]);
            float v0 = s.x * ew, v1 = s.y * ew;
            if (v0 > d.x) atomicMax(dn + 2 * j + 0, __float_as_uint(v0));
            if (v1 > d.y) atomicMax(dn + 2 * j + 1, __float_as_uint(v1));
        }
    }
}

// ---------------- kernel 3: convert n32 -> c16 (both branches) ------------
__global__ void convert_kernel() {
    int i = blockIdx.x * blockDim.x + threadIdx.x;
    const int n4 = NN * MDIM / 4;
    if (i >= n4) return;
    float4 p = reinterpret_cast<const float4*>(g_n32pos)[i];
    float4 d = reinterpret_cast<const float4*>(g_n32dom)[i];
    __half2 p0 = __floats2half2_rn(p.x, p.y);
    __half2 p1 = __floats2half2_rn(p.z, p.w);
    __half2 d0 = __floats2half2_rn(d.x, d.y);
    __half2 d1 = __floats2half2_rn(d.z, d.w);
    reinterpret_cast<uint2*>(g_c16pos)[i] =
        make_uint2(*reinterpret_cast<unsigned*>(&p0), *reinterpret_cast<unsigned*>(&p1));
    reinterpret_cast<uint2*>(g_c16dom)[i] =
        make_uint2(*reinterpret_cast<unsigned*>(&d0), *reinterpret_cast<unsigned*>(&d1));
}

// ---------------- kernel 4: propagation rounds 2-3 -------------------------
// 2 lanes per edge, 2 edges per thread (one spatial + one dom), all four row
// loads front-batched for MLP=4. ES == ED is assumed by the pairing.
__global__ void prop_kernel(const int* __restrict__ si, const int* __restrict__ di) {
    long long t = (long long)blockIdx.x * blockDim.x + threadIdx.x;
    if (t >= (long long)ES * 2) return;
    int p = (int)(t >> 1);       // edge id in each set
    int sub = (int)(t & 1);      // half-row (8 channels)

    int s0 = si[p], d0 = si[ES + p];
    int s1 = di[p], d1 = di[ED + p];
    float ew0 = g_ew_s[p];
    float ew1 = g_ew_d[p];

    uint4 sr0 = *reinterpret_cast<const uint4*>(&g_c16pos[(size_t)s0 * MDIM + sub * 8]);
    uint4 dr0 = *reinterpret_cast<const uint4*>(&g_c16pos[(size_t)d0 * MDIM + sub * 8]);
    uint4 sr1 = *reinterpret_cast<const uint4*>(&g_c16dom[(size_t)s1 * MDIM + sub * 8]);
    uint4 dr1 = *reinterpret_cast<const uint4*>(&g_c16dom[(size_t)d1 * MDIM + sub * 8]);

    {
        const __half2* sh = reinterpret_cast<const __half2*>(&sr0);
        const __half2* dh = reinterpret_cast<const __half2*>(&dr0);
        unsigned int* dn = reinterpret_cast<unsigned int*>(&g_n32pos[(size_t)d0 * MDIM + sub * 8]);
#pragma unroll
        for (int j = 0; j < 4; j++) {
            float2 s = __half22float2(sh[j]);
            float2 d = __half22float2(dh[j]);
            float v0 = s.x * ew0, v1 = s.y * ew0;
            if (v0 > d.x) atomicMax(dn + 2 * j + 0, __float_as_uint(v0));
            if (v1 > d.y) atomicMax(dn + 2 * j + 1, __float_as_uint(v1));
        }
    }
    {
        const __half2* sh = reinterpret_cast<const __half2*>(&sr1);
        const __half2* dh = reinterpret_cast<const __half2*>(&dr1);
        unsigned int* dn = reinterpret_cast<unsigned int*>(&g_n32dom[(size_t)d1 * MDIM + sub * 8]);
#pragma unroll
        for (int j = 0; j < 4; j++) {
            float2 s = __half22float2(sh[j]);
            float2 d = __half22float2(dh[j]);
            float v0 = s.x * ew1, v1 = s.y * ew1;
            if (v0 > d.x) atomicMax(dn + 2 * j + 0, __float_as_uint(v0));
            if (v1 > d.y) atomicMax(dn + 2 * j + 1, __float_as_uint(v1));
        }
    }
}

// ---------------- kernel 5: final max --------------------------------------
__global__ void final_kernel(const float* __restrict__ mask, float* __restrict__ out) {
    int i = blockIdx.x * blockDim.x + threadIdx.x;
    const int n4 = NN * MDIM / 4;
    if (i >= n4) return;
    float4 m = reinterpret_cast<const float4*>(mask)[i];
    float4 p = reinterpret_cast<const float4*>(g_n32pos)[i];
    float4 d = reinterpret_cast<const float4*>(g_n32dom)[i];
    float4 r;
    r.x = fmaxf(m.x, fmaxf(p.x, d.x));
    r.y = fmaxf(m.y, fmaxf(p.y, d.y));
    r.z = fmaxf(m.z, fmaxf(p.z, d.z));
    r.w = fmaxf(m.w, fmaxf(p.w, d.w));
    reinterpret_cast<float4*>(out)[i] = r;
}

// ---------------- launch -------------------------------------------------
extern "C" void kernel_launch(void* const* d_in, const int* in_sizes, int n_in,
                              void* d_out, int out_size) {
    const float* x     = (const float*)d_in[0];
    const float* mask  = (const float*)d_in[1];
    const int*   si    = (const int*)d_in[2];
    const int*   di    = (const int*)d_in[3];
    const float* sattr = (const float*)d_in[4];
    const float* dattr = (const float*)d_in[5];
    const float* Wt    = (const float*)d_in[6];
    const float* bt    = (const float*)d_in[7];
    const float* Wpos  = (const float*)d_in[8];
    const float* bpos  = (const float*)d_in[9];
    const float* Wdom  = (const float*)d_in[10];
    const float* bdom  = (const float*)d_in[11];
    float* out = (float*)d_out;

    const int n4 = NN * MDIM / 4;
    const int cgrid = (n4 + 255) / 256;

    // 1. HMMA node projections + fused mask-buffer init
    proj_kernel<<<(NN + 63) / 64, 128>>>(x, Wt, bt, mask);

    // 2. fused gate + propagation round 1
    {
        long long threads = (long long)(ES + ED) * 4;
        int blk = 256;
        long long grid = (threads + blk - 1) / blk;
        ewprop_kernel<<<(unsigned)grid, blk>>>(si, di, sattr, dattr, Wpos, bpos, Wdom, bdom);
    }

    // 3. rounds 2-3: convert / prop / convert / prop
    {
        long long threads = (long long)ES * 2;   // 2 edges (one per set) per thread
        int blk = 256;
        long long grid = (threads + blk - 1) / blk;

        convert_kernel<<<cgrid, 256>>>();
        prop_kernel<<<(unsigned)grid, blk>>>(si, di);
        convert_kernel<<<cgrid, 256>>>();
        prop_kernel<<<(unsigned)grid, blk>>>(si, di);
    }

    // 4. final: max(mask, pos, dom)
    final_kernel<<<cgrid, 256>>>(mask, out);
}

// round 12
// speedup vs baseline: 1.5397x; 1.0022x over previous
#include <cuda_runtime.h>
#include <cuda_fp16.h>
#include <cstdint>

#define NN     100000
#define HH     128
#define TT     32
#define MDIM   16
#define ES     600000
#define ED     600000

// ---------------- scratch ----------------
__device__ __align__(16) __half g_Ps[NN * TT];   // fp16 x@W[:H]
__device__ __align__(16) __half g_Pd[NN * TT];   // fp16 x@W[H:] + b_trans
__device__ float g_ew_s[ES];
__device__ float g_ew_d[ED];
// propagation state: fp32 accumulator (atomics) + fp16 read mirror
__device__ __align__(16) float  g_n32pos[NN * MDIM];
__device__ __align__(16) float  g_n32dom[NN * MDIM];
__device__ __align__(16) __half g_c16pos[NN * MDIM];
__device__ __align__(16) __half g_c16dom[NN * MDIM];

// ---------------- helpers ----------------
__device__ __forceinline__ float fast_tanh(float s) {
    float r; asm("tanh.approx.f32 %0, %1;" : "=f"(r) : "f"(s)); return r;
}
__device__ __forceinline__ unsigned su32(const void* p) {
    return (unsigned)__cvta_generic_to_shared(p);
}

// ---------------- kernel 1: HMMA node projections + fused init -------------
#define XS_STRIDE 136
#define WP_STRIDE 72

__global__ void __launch_bounds__(128) proj_kernel(const float* __restrict__ x,
                                                   const float* __restrict__ Wt,
                                                   const float* __restrict__ bt,
                                                   const float* __restrict__ mask) {
    __shared__ __align__(16) __half Wp[128 * WP_STRIDE];
    __shared__ __align__(16) __half xs[64 * XS_STRIDE];
    int tid = threadIdx.x;
    int n0 = blockIdx.x * 64;

    // ---- fused init: mask -> n32 (fp32) + c16 (fp16), grid-stride ----
    {
        const int n4 = NN * MDIM / 4;
        for (int i = blockIdx.x * 128 + tid; i < n4; i += gridDim.x * 128) {
            float4 v = reinterpret_cast<const float4*>(mask)[i];
            reinterpret_cast<float4*>(g_n32pos)[i] = v;
            reinterpret_cast<float4*>(g_n32dom)[i] = v;
            __half2 h0 = __floats2half2_rn(v.x, v.y);
            __half2 h1 = __floats2half2_rn(v.z, v.w);
            uint2 packed = make_uint2(*reinterpret_cast<unsigned*>(&h0),
                                      *reinterpret_cast<unsigned*>(&h1));
            reinterpret_cast<uint2*>(g_c16pos)[i] = packed;
            reinterpret_cast<uint2*>(g_c16dom)[i] = packed;
        }
    }

    for (int i = tid; i < 128 * 64; i += 128) {
        int h = i >> 6, j = i & 63;
        float w = (j < 32) ? Wt[h * 32 + j] : Wt[(128 + h) * 32 + (j - 32)];
        Wp[h * WP_STRIDE + j] = __float2half_rn(w);
    }
    for (int i = tid; i < 64 * 32; i += 128) {
        int r = i >> 5, c4 = i & 31;
        int node = n0 + r;
        float4 v = (node < NN)
                 ? reinterpret_cast<const float4*>(x)[(size_t)node * 32 + c4]
                 : make_float4(0.f, 0.f, 0.f, 0.f);
        *reinterpret_cast<__half2*>(&xs[r * XS_STRIDE + c4 * 4])     = __floats2half2_rn(v.x, v.y);
        *reinterpret_cast<__half2*>(&xs[r * XS_STRIDE + c4 * 4 + 2]) = __floats2half2_rn(v.z, v.w);
    }
    __syncthreads();

    int warp = tid >> 5, lane = tid & 31;
    int wb = warp * 16;

    float acc[8][4];
#pragma unroll
    for (int nt = 0; nt < 8; nt++)
#pragma unroll
        for (int j = 0; j < 4; j++) acc[nt][j] = 0.f;

    int a_row = wb + (lane & 15);
    int a_coff = (lane >> 4) * 8;
    int b_row = (lane & 15);

#pragma unroll
    for (int k = 0; k < 8; k++) {
        unsigned a0, a1, a2, a3;
        unsigned addrA = su32(&xs[a_row * XS_STRIDE + k * 16 + a_coff]);
        asm volatile("ldmatrix.sync.aligned.m8n8.x4.shared.b16 {%0,%1,%2,%3}, [%4];"
                     : "=r"(a0), "=r"(a1), "=r"(a2), "=r"(a3) : "r"(addrA));
#pragma unroll
        for (int nt = 0; nt < 8; nt++) {
            unsigned b0, b1;
            unsigned addrB = su32(&Wp[(k * 16 + b_row) * WP_STRIDE + nt * 8]);
            asm volatile("ldmatrix.sync.aligned.m8n8.x2.trans.shared.b16 {%0,%1}, [%2];"
                         : "=r"(b0), "=r"(b1) : "r"(addrB));
            asm volatile("mma.sync.aligned.m16n8k16.row.col.f32.f16.f16.f32 "
                         "{%0,%1,%2,%3}, {%4,%5,%6,%7}, {%8,%9}, {%0,%1,%2,%3};"
                         : "+f"(acc[nt][0]), "+f"(acc[nt][1]), "+f"(acc[nt][2]), "+f"(acc[nt][3])
                         : "r"(a0), "r"(a1), "r"(a2), "r"(a3), "r"(b0), "r"(b1));
        }
    }

    int row_l = wb + (lane >> 2);
    int col0 = (lane & 3) * 2;
#pragma unroll
    for (int nt = 0; nt < 8; nt++) {
        bool isPs = (nt < 4);
        __half* base = isPs ? g_Ps : g_Pd;
        int cc = isPs ? (nt * 8 + col0) : (nt * 8 + col0 - 32);
        float b0 = isPs ? 0.f : bt[cc];
        float b1 = isPs ? 0.f : bt[cc + 1];
        int nodeA = n0 + row_l;
        int nodeB = nodeA + 8;
        if (nodeA < NN)
            *reinterpret_cast<__half2*>(&base[(size_t)nodeA * TT + cc]) =
                __floats2half2_rn(acc[nt][0] + b0, acc[nt][1] + b1);
        if (nodeB < NN)
            *reinterpret_cast<__half2*>(&base[(size_t)nodeB * TT + cc]) =
                __floats2half2_rn(acc[nt][2] + b0, acc[nt][3] + b1);
    }
}

// ---------------- kernel 2: FUSED gate + propagation round 1 ---------------
// 2 lanes/edge: each lane covers 16 channels (2x uint4 per row, front-batched
// for MLP=4), one shfl to reduce, then 8 channels/lane of round-1 propagation.
__global__ void ewprop_kernel(const int* __restrict__ si, const int* __restrict__ di,
                              const float* __restrict__ sattr, const float* __restrict__ dattr,
                              const float* __restrict__ Wpos, const float* __restrict__ bpos,
                              const float* __restrict__ Wdom, const float* __restrict__ bdom) {
    long long gid = (long long)blockIdx.x * blockDim.x + threadIdx.x;
    long long eg = gid >> 1;
    int sub = (int)(gid & 1);      // half: channels [sub*16, sub*16+16)
    if (eg >= (long long)(ES + ED)) return;

    bool spatial = (eg < ES);
    int e = spatial ? (int)eg : (int)(eg - ES);
    const int* eidx = spatial ? si : di;
    int nE = spatial ? ES : ED;
    int src = eidx[e];
    int dst = eidx[nE + e];

    const __half* psrow = &g_Ps[(size_t)src * TT + sub * 16];
    const __half* pdrow = &g_Pd[(size_t)dst * TT + sub * 16];
    uint4 pa0 = *reinterpret_cast<const uint4*>(psrow);
    uint4 pa1 = *reinterpret_cast<const uint4*>(psrow + 8);
    uint4 pb0 = *reinterpret_cast<const uint4*>(pdrow);
    uint4 pb1 = *reinterpret_cast<const uint4*>(pdrow + 8);
    const __half2* ph0 = reinterpret_cast<const __half2*>(&pa0);
    const __half2* ph1 = reinterpret_cast<const __half2*>(&pa1);
    const __half2* qh0 = reinterpret_cast<const __half2*>(&pb0);
    const __half2* qh1 = reinterpret_cast<const __half2*>(&pb1);

    float th[16];
#pragma unroll
    for (int j = 0; j < 4; j++) {
        float2 a = __half22float2(ph0[j]);
        float2 b = __half22float2(qh0[j]);
        th[2 * j]     = fast_tanh(a.x + b.x);
        th[2 * j + 1] = fast_tanh(a.y + b.y);
        float2 c = __half22float2(ph1[j]);
        float2 d = __half22float2(qh1[j]);
        th[8 + 2 * j]     = fast_tanh(c.x + d.x);
        th[8 + 2 * j + 1] = fast_tanh(c.y + d.y);
    }

    float part = 0.f;
    if (spatial) {
        const float* w = &Wpos[4 + sub * 16];
#pragma unroll
        for (int j = 0; j < 16; j++) part += th[j] * w[j];
        if (sub == 0) {
            float4 a = *reinterpret_cast<const float4*>(&sattr[(size_t)e * 4]);
            part += a.x * Wpos[0] + a.y * Wpos[1] + a.z * Wpos[2] + a.w * Wpos[3];
        }
    } else {
        const float* w = &Wdom[1 + sub * 16];
#pragma unroll
        for (int j = 0; j < 16; j++) part += th[j] * w[j];
        if (sub == 0) part += dattr[e] * Wdom[0];
    }

    part += __shfl_xor_sync(0xFFFFFFFFu, part, 1);

    float logit = part + (spatial ? bpos[0] : bdom[0]);
    float ew = 1.f / (1.f + __expf(-logit));
    if (sub == 0) { if (spatial) g_ew_s[e] = ew; else g_ew_d[e] = ew; }

    // ---- fused round-1 propagation: 2 lanes x 8 channels ----
    {
        const __half* c = spatial ? g_c16pos : g_c16dom;
        float* n = spatial ? g_n32pos : g_n32dom;
        uint4 sr = *reinterpret_cast<const uint4*>(&c[(size_t)src * MDIM + sub * 8]);
        uint4 dr = *reinterpret_cast<const uint4*>(&c[(size_t)dst * MDIM + sub * 8]);
        const __half2* sh = reinterpret_cast<const __half2*>(&sr);
        const __half2* dh = reinterpret_cast<const __half2*>(&dr);
        unsigned int* dn = reinterpret_cast<unsigned int*>(&n[(size_t)dst * MDIM + sub * 8]);
#pragma unroll
        for (int j = 0; j < 4; j++) {
            float2 s = __half22float2(sh[j]);
            float2 d = __half22float2(dh[j]);
            float v0 = s.x * ew, v1 = s.y * ew;
            if (v0 > d.x) atomicMax(dn + 2 * j + 0, __float_as_uint(v0));
            if (v1 > d.y) atomicMax(dn + 2 * j + 1, __float_as_uint(v1));
        }
    }
}

// ---------------- kernel 3: convert n32 -> c16 (both branches) ------------
__global__ void convert_kernel() {
    int i = blockIdx.x * blockDim.x + threadIdx.x;
    const int n4 = NN * MDIM / 4;
    if (i >= n4) return;
    float4 p = reinterpret_cast<const float4*>(g_n32pos)[i];
    float4 d = reinterpret_cast<const float4*>(g_n32dom)[i];
    __half2 p0 = __floats2half2_rn(p.x, p.y);
    __half2 p1 = __floats2half2_rn(p.z, p.w);
    __half2 d0 = __floats2half2_rn(d.x, d.y);
    __half2 d1 = __floats2half2_rn(d.z, d.w);
    reinterpret_cast<uint2*>(g_c16pos)[i] =
        make_uint2(*reinterpret_cast<unsigned*>(&p0), *reinterpret_cast<unsigned*>(&p1));
    reinterpret_cast<uint2*>(g_c16dom)[i] =
        make_uint2(*reinterpret_cast<unsigned*>(&d0), *reinterpret_cast<unsigned*>(&d1));
}

// ---------------- kernel 4: propagation rounds 2-3 -------------------------
__global__ void prop_kernel(const int* __restrict__ si, const int* __restrict__ di) {
    long long t = (long long)blockIdx.x * blockDim.x + threadIdx.x;
    if (t >= (long long)ES * 2) return;
    int p = (int)(t >> 1);       // edge id in each set
    int sub = (int)(t & 1);      // half-row (8 channels)

    int s0 = si[p], d0 = si[ES + p];
    int s1 = di[p], d1 = di[ED + p];
    float ew0 = g_ew_s[p];
    float ew1 = g_ew_d[p];

    uint4 sr0 = *reinterpret_cast<const uint4*>(&g_c16pos[(size_t)s0 * MDIM + sub * 8]);
    uint4 dr0 = *reinterpret_cast<const uint4*>(&g_c16pos[(size_t)d0 * MDIM + sub * 8]);
    uint4 sr1 = *reinterpret_cast<const uint4*>(&g_c16dom[(size_t)s1 * MDIM + sub * 8]);
    uint4 dr1 = *reinterpret_cast<const uint4*>(&g_c16dom[(size_t)d1 * MDIM + sub * 8]);

    {
        const __half2* sh = reinterpret_cast<const __half2*>(&sr0);
        const __half2* dh = reinterpret_cast<const __half2*>(&dr0);
        unsigned int* dn = reinterpret_cast<unsigned int*>(&g_n32pos[(size_t)d0 * MDIM + sub * 8]);
#pragma unroll
        for (int j = 0; j < 4; j++) {
            float2 s = __half22float2(sh[j]);
            float2 d = __half22float2(dh[j]);
            float v0 = s.x * ew0, v1 = s.y * ew0;
            if (v0 > d.x) atomicMax(dn + 2 * j + 0, __float_as_uint(v0));
            if (v1 > d.y) atomicMax(dn + 2 * j + 1, __float_as_uint(v1));
        }
    }
    {
        const __half2* sh = reinterpret_cast<const __half2*>(&sr1);
        const __half2* dh = reinterpret_cast<const __half2*>(&dr1);
        unsigned int* dn = reinterpret_cast<unsigned int*>(&g_n32dom[(size_t)d1 * MDIM + sub * 8]);
#pragma unroll
        for (int j = 0; j < 4; j++) {
            float2 s = __half22float2(sh[j]);
            float2 d = __half22float2(dh[j]);
            float v0 = s.x * ew1, v1 = s.y * ew1;
            if (v0 > d.x) atomicMax(dn + 2 * j + 0, __float_as_uint(v0));
            if (v1 > d.y) atomicMax(dn + 2 * j + 1, __float_as_uint(v1));
        }
    }
}

// ---------------- kernel 5: final max --------------------------------------
__global__ void final_kernel(const float* __restrict__ mask, float* __restrict__ out) {
    int i = blockIdx.x * blockDim.x + threadIdx.x;
    const int n4 = NN * MDIM / 4;
    if (i >= n4) return;
    float4 m = reinterpret_cast<const float4*>(mask)[i];
    float4 p = reinterpret_cast<const float4*>(g_n32pos)[i];
    float4 d = reinterpret_cast<const float4*>(g_n32dom)[i];
    float4 r;
    r.x = fmaxf(m.x, fmaxf(p.x, d.x));
    r.y = fmaxf(m.y, fmaxf(p.y, d.y));
    r.z = fmaxf(m.z, fmaxf(p.z, d.z));
    r.w = fmaxf(m.w, fmaxf(p.w, d.w));
    reinterpret_cast<float4*>(out)[i] = r;
}

// ---------------- launch -------------------------------------------------
extern "C" void kernel_launch(void* const* d_in, const int* in_sizes, int n_in,
                              void* d_out, int out_size) {
    const float* x     = (const float*)d_in[0];
    const float* mask  = (const float*)d_in[1];
    const int*   si    = (const int*)d_in[2];
    const int*   di    = (const int*)d_in[3];
    const float* sattr = (const float*)d_in[4];
    const float* dattr = (const float*)d_in[5];
    const float* Wt    = (const float*)d_in[6];
    const float* bt    = (const float*)d_in[7];
    const float* Wpos  = (const float*)d_in[8];
    const float* bpos  = (const float*)d_in[9];
    const float* Wdom  = (const float*)d_in[10];
    const float* bdom  = (const float*)d_in[11];
    float* out = (float*)d_out;

    const int n4 = NN * MDIM / 4;
    const int cgrid = (n4 + 255) / 256;

    // 1. HMMA node projections + fused mask-buffer init
    proj_kernel<<<(NN + 63) / 64, 128>>>(x, Wt, bt, mask);

    // 2. fused gate + propagation round 1 (2 lanes/edge)
    {
        long long threads = (long long)(ES + ED) * 2;
        int blk = 256;
        long long grid = (threads + blk - 1) / blk;
        ewprop_kernel<<<(unsigned)grid, blk>>>(si, di, sattr, dattr, Wpos, bpos, Wdom, bdom);
    }

    // 3. rounds 2-3: convert / prop / convert / prop
    {
        long long threads = (long long)ES * 2;   // 2 edges (one per set) per thread
        int blk = 256;
        long long grid = (threads + blk - 1) / blk;

        convert_kernel<<<cgrid, 256>>>();
        prop_kernel<<<(unsigned)grid, blk>>>(si, di);
        convert_kernel<<<cgrid, 256>>>();
        prop_kernel<<<(unsigned)grid, blk>>>(si, di);
    }

    // 4. final: max(mask, pos, dom)
    final_kernel<<<cgrid, 256>>>(mask, out);
}